// round 15
// baseline (speedup 1.0000x reference)
#include <cuda_runtime.h>

// QnnFormerVQC round 15: SINGLE kernel, makespan-balanced chunk distribution.
//  - grid = 296 blocks (= 2 x 148 SMs = exactly the 2-resident/SM capacity at
//    ~100 regs): one wave, no wave transitions. total_chunks (=1024 for B) is
//    split contiguously: base=3 chunks/block, first `rem` blocks take 4.
//    Contiguous-modular CLC placement pairs block b with b+148 on one SM ->
//    (4,3)-chunk pairs -> max 7 chunks/SM instead of 8 (round-14 imbalance).
//  - Per block: parameter tables (__sincosf, parallel), then all 8 warps build
//    the fixed 16x16 circuit unitary W via warp-shuffle butterflies (one
//    amplitude per lane, 2 columns per warp) -> Wsh.
//  - Per chunk (software-pipelined input loads): p = real encoding tensor;
//    psi = W @ p (512 FMA, broadcast LDS.128 rows); measurement with RX(beta2)
//    folded in (z'=cb*z+sb*y, y'=cb*y-sb*z, x'=x; T==1 by unitarity).
// Circuit reductions (verified vs round-3 literal oracle):
//  - RZ*RY*RX(w) -> one 2x2 matrix U per (L,q); RX(beta0/1) folded into the
//    next layer's U. Reference's _apmcx == swap amplitudes 7<->15, so the
//    H/X/MCX block == psi_i -= sum(psi9,11,13,15)/2 on {9,11,13,15}.
//  - CX-RZ(gamma)-CX chain == 16-entry diagonal phase table.
// Bit convention: qubit q <-> mask (8 >> q), qubit 0 = MSB.

#define NQ 4
#define NL 3
#define TPB 256
#define TARGET_BLOCKS 296   // 2 x 148 SMs

struct PS {
    float2 U[NL][NQ][2][2];
    float  ce[NL][NQ], se[NL][NQ];
    float2 dg[NL][16];
};

__device__ __forceinline__ float2 cmulh(float2 a, float2 b) {
    return make_float2(a.x * b.x - a.y * b.y, a.x * b.y + a.y * b.x);
}
__device__ __forceinline__ float2 caddh(float2 a, float2 b) {
    return make_float2(a.x + b.x, a.y + b.y);
}

__global__ void __launch_bounds__(TPB)
vqc_kernel(const float4* __restrict__ x,
           float* __restrict__ out,
           const float* __restrict__ w,
           const float* __restrict__ ew,
           const float* __restrict__ gam,
           const float* __restrict__ bet,
           int n, int total_chunks) {
    __shared__ PS ps;
    __shared__ float2 Wsh[16][16];
    __shared__ float2 mbsh;

    int t = threadIdx.x;
    int bid = blockIdx.x;
    int nb = gridDim.x;

    // contiguous chunk range for this block
    int base = total_chunks / nb;
    int rem  = total_chunks % nb;
    int cnt   = base + (bid < rem ? 1 : 0);
    int start = bid * base + (bid < rem ? bid : rem);

    // ---- prefetch first chunk's input (hidden behind tables + evolution) ----
    int e0 = start * TPB + t;
    bool act0 = (cnt > 0) && (e0 < n);
    float4 xv_cur = act0 ? x[e0] : make_float4(0.f, 0.f, 0.f, 0.f);

    // ---- parameter tables (per block, parallel, __sincosf) ----
    if (t < NL * NQ) {
        int L = t / NQ, q = t % NQ;
        float th = w[L * NQ + q];
        float c, s;
        __sincosf(0.5f * th, &s, &c);
        float2 RX[2][2] = {{{c, 0.f}, {0.f, -s}}, {{0.f, -s}, {c, 0.f}}};
        float2 RY[2][2] = {{{c, 0.f}, {-s, 0.f}}, {{s, 0.f}, {c, 0.f}}};
        float2 RZ[2][2] = {{{c, -s}, {0.f, 0.f}}, {{0.f, 0.f}, {c, s}}};
        float2 T[2][2], M[2][2];
        #pragma unroll
        for (int i = 0; i < 2; i++)
            #pragma unroll
            for (int j = 0; j < 2; j++)
                T[i][j] = caddh(cmulh(RY[i][0], RX[0][j]),
                                cmulh(RY[i][1], RX[1][j]));
        #pragma unroll
        for (int i = 0; i < 2; i++)
            #pragma unroll
            for (int j = 0; j < 2; j++)
                M[i][j] = caddh(cmulh(RZ[i][0], T[0][j]),
                                cmulh(RZ[i][1], T[1][j]));
        if (L > 0) {  // fold previous layer's RX(beta): M_eff = M * RXb
            float cb, sb;
            __sincosf(0.5f * bet[L - 1], &sb, &cb);
            float2 RXb[2][2] = {{{cb, 0.f}, {0.f, -sb}},
                                {{0.f, -sb}, {cb, 0.f}}};
            float2 E[2][2];
            #pragma unroll
            for (int i = 0; i < 2; i++)
                #pragma unroll
                for (int j = 0; j < 2; j++)
                    E[i][j] = caddh(cmulh(M[i][0], RXb[0][j]),
                                    cmulh(M[i][1], RXb[1][j]));
            #pragma unroll
            for (int i = 0; i < 2; i++)
                #pragma unroll
                for (int j = 0; j < 2; j++)
                    M[i][j] = E[i][j];
        }
        #pragma unroll
        for (int i = 0; i < 2; i++)
            #pragma unroll
            for (int j = 0; j < 2; j++)
                ps.U[L][q][i][j] = M[i][j];
        __sincosf(0.5f * ew[L * NQ + q], &ps.se[L][q], &ps.ce[L][q]);
    }
    if (t >= 16 && t < 16 + NL * 16) {
        int r = t - 16;
        int L = r / 16, idx = r % 16;
        int k = 0;
        #pragma unroll
        for (int i = 0; i < 3; i++) {
            int bi = (idx >> (3 - i)) & 1;
            int bj = (idx >> (2 - i)) & 1;
            if (bi == bj) k++;
        }
        float ang = 0.5f * gam[L] * (float)(3 - 2 * k);
        float sa, ca;
        __sincosf(ang, &sa, &ca);
        ps.dg[L][idx] = make_float2(ca, sa);
    }
    if (t == 64) {
        float cb, sb;
        __sincosf(bet[NL - 1], &sb, &cb);  // FULL angle
        mbsh = make_float2(cb, sb);
    }
    __syncthreads();

    // ---- warp-shuffle basis evolution: all 8 warps, 2 columns each ----
    {
        int lane = t & 31;
        int i = lane & 15;                       // amplitude index
        int col = ((t >> 5) << 1) | (lane >> 4); // basis column 0..15
        float ax = (i == col) ? 1.f : 0.f;
        float ay = 0.f;

        #pragma unroll
        for (int L = 0; L < NL; L++) {
            // combined single-qubit U per qubit (butterfly over mask)
            #pragma unroll
            for (int q = 0; q < NQ; q++) {
                int m = 8 >> q;
                float2 u00 = ps.U[L][q][0][0], u01 = ps.U[L][q][0][1];
                float2 u10 = ps.U[L][q][1][0], u11 = ps.U[L][q][1][1];
                bool bit = (i & m) != 0;
                float csx = bit ? u11.x : u00.x, csy = bit ? u11.y : u00.y;
                float cpx = bit ? u10.x : u01.x, cpy = bit ? u10.y : u01.y;
                float px = __shfl_xor_sync(0xffffffffu, ax, m);
                float py = __shfl_xor_sync(0xffffffffu, ay, m);
                float nr = csx * ax;
                nr = fmaf(-csy, ay, nr);
                nr = fmaf(cpx, px, nr);
                nr = fmaf(-cpy, py, nr);
                float ni = csx * ay;
                ni = fmaf(csy, ax, ni);
                ni = fmaf(cpx, py, ni);
                ni = fmaf(cpy, px, ni);
                ax = nr; ay = ni;
            }
            // cRX ring: control q, target (q+1)%4 (RX symmetric -> uniform)
            #pragma unroll
            for (int q = 0; q < NQ; q++) {
                int cm = 8 >> q;
                int tm = 8 >> ((q + 1) & 3);
                float c = ps.ce[L][q], s = ps.se[L][q];
                bool on = (i & cm) != 0;
                float ce_ = on ? c : 1.f;
                float se_ = on ? s : 0.f;
                float px = __shfl_xor_sync(0xffffffffu, ax, tm);
                float py = __shfl_xor_sync(0xffffffffu, ay, tm);
                float nr = fmaf(ce_, ax, se_ * py);
                float ni = fmaf(ce_, ay, -se_ * px);
                ax = nr; ay = ni;
            }
            // diffuser: psi_i -= (psi9+psi11+psi13+psi15)/2, i in {9,11,13,15}
            {
                bool sel = ((i & 9) == 9);
                float h = sel ? 0.5f : 0.f;
                float vx = sel ? ax : 0.f;
                float vy = sel ? ay : 0.f;
                vx += __shfl_xor_sync(0xffffffffu, vx, 2);
                vy += __shfl_xor_sync(0xffffffffu, vy, 2);
                vx += __shfl_xor_sync(0xffffffffu, vx, 4);
                vy += __shfl_xor_sync(0xffffffffu, vy, 4);
                ax = fmaf(-h, vx, ax);
                ay = fmaf(-h, vy, ay);
            }
            // RZZ diagonal phase
            {
                float2 ph = ps.dg[L][i];
                float nr = ph.x * ax; nr = fmaf(-ph.y, ay, nr);
                float ni = ph.x * ay; ni = fmaf(ph.y, ax, ni);
                ax = nr; ay = ni;
            }
        }
        Wsh[i][col] = make_float2(ax, ay);
    }
    __syncthreads();

    float cb = mbsh.x, sb = mbsh.y;

    // ---- chunk loop (software-pipelined input loads) ----
    for (int c = 0; c < cnt; c++) {
        // prefetch next chunk's input
        int en = (start + c + 1) * TPB + t;
        bool actn = (c + 1 < cnt) && (en < n);
        float4 xv_next = actn ? x[en] : make_float4(0.f, 0.f, 0.f, 0.f);

        int e = (start + c) * TPB + t;
        if (e < n) {
            // encode: p = tensor_q (cos x_q/2, sin x_q/2), real
            float p[16];
            {
                float cq[4], sq[4];
                __sincosf(0.5f * xv_cur.x, &sq[0], &cq[0]);
                __sincosf(0.5f * xv_cur.y, &sq[1], &cq[1]);
                __sincosf(0.5f * xv_cur.z, &sq[2], &cq[2]);
                __sincosf(0.5f * xv_cur.w, &sq[3], &cq[3]);
                float a01[4], a012[8];
                a01[0] = cq[0] * cq[1]; a01[1] = cq[0] * sq[1];
                a01[2] = sq[0] * cq[1]; a01[3] = sq[0] * sq[1];
                #pragma unroll
                for (int k = 0; k < 4; k++) {
                    a012[2 * k]     = a01[k] * cq[2];
                    a012[2 * k + 1] = a01[k] * sq[2];
                }
                #pragma unroll
                for (int m = 0; m < 8; m++) {
                    p[2 * m]     = a012[m] * cq[3];
                    p[2 * m + 1] = a012[m] * sq[3];
                }
            }

            // psi = W @ p (complex x real matvec, 512 FMA)
            float2 psi[16];
            #pragma unroll
            for (int i = 0; i < 16; i++) {
                const float4* row = reinterpret_cast<const float4*>(&Wsh[i][0]);
                float re = 0.f, im = 0.f;
                #pragma unroll
                for (int jj = 0; jj < 8; jj++) {
                    float4 v = row[jj];  // (W[i][2jj].re,.im, W[i][2jj+1].re,.im)
                    re = fmaf(v.x, p[2 * jj], re);
                    im = fmaf(v.y, p[2 * jj], im);
                    re = fmaf(v.z, p[2 * jj + 1], re);
                    im = fmaf(v.w, p[2 * jj + 1], im);
                }
                psi[i] = make_float2(re, im);
            }

            // measurement with RX(beta2) fold; T == 1 by unitarity
            float sq2[16];
            #pragma unroll
            for (int i = 0; i < 16; i++)
                sq2[i] = fmaf(psi[i].x, psi[i].x, psi[i].y * psi[i].y);

            float res[12];
            #pragma unroll
            for (int q = 0; q < NQ; q++) {
                int mask = 8 >> q;
                float s1 = 0.f;
                #pragma unroll
                for (int i = 0; i < 16; i++)
                    if (i & mask) s1 += sq2[i];
                float z = fmaf(-2.f, s1, 1.f);

                float xr = 0.f, yi = 0.f;
                #pragma unroll
                for (int i = 0; i < 16; i++) {
                    if (i & mask) continue;
                    int j = i | mask;
                    float2 a = psi[i], d = psi[j];
                    xr = fmaf(a.x, d.x, xr); xr = fmaf(a.y, d.y, xr);
                    yi = fmaf(a.x, d.y, yi); yi = fmaf(-a.y, d.x, yi);
                }
                float xo = 2.f * xr, yo = 2.f * yi;
                res[q]     = fmaf(cb, z, sb * yo);      // z' = cb*z + sb*y
                res[4 + q] = xo;                        // x' = x
                res[8 + q] = fmaf(cb, yo, -sb * z);     // y' = cb*y - sb*z
            }

            float4* o = reinterpret_cast<float4*>(out + (size_t)e * 12);
            o[0] = make_float4(res[0], res[1], res[2],  res[3]);
            o[1] = make_float4(res[4], res[5], res[6],  res[7]);
            o[2] = make_float4(res[8], res[9], res[10], res[11]);
        }

        xv_cur = xv_next;
    }
}

extern "C" void kernel_launch(void* const* d_in, const int* in_sizes, int n_in,
                              void* d_out, int out_size) {
    const float* x   = (const float*)d_in[0];  // (B, 4)
    const float* w   = (const float*)d_in[1];  // (3, 4)
    const float* ew  = (const float*)d_in[2];  // (3, 4)
    const float* gam = (const float*)d_in[3];  // (3,)
    const float* bet = (const float*)d_in[4];  // (3,)
    float* out = (float*)d_out;                // (B, 12)

    int n = in_sizes[0] / 4;
    int total_chunks = (n + TPB - 1) / TPB;
    int blocks = total_chunks < TARGET_BLOCKS ? total_chunks : TARGET_BLOCKS;

    vqc_kernel<<<blocks, TPB>>>((const float4*)x, out, w, ew, gam, bet,
                                n, total_chunks);
}

// round 16
// speedup vs baseline: 1.1173x; 1.1173x over previous
#include <cuda_runtime.h>

// QnnFormerVQC round 16: round-14 static-unroll structure + balanced mapping.
//  - grid = 296 blocks (2 x 148 SMs = exact 2-resident capacity at ~100 regs;
//    single wave). 1024 chunks split: first 136 blocks take 4, rest take 3
//    (start = 3*bid + min(bid,136)). Contiguous-modular placement pairs block
//    b with b+148 on one SM -> (4,3)/(3,3) pairs -> max 7 chunks/SM (was 8).
//  - STATIC #pragma unroll CHUNKS=4 loop with per-chunk act[] predicates and
//    prefetch-all inputs (the round-14 shape that compiled to 101 regs);
//    NO dynamic pipelined loop (round-15's 192-reg trap).
//  - Per block: parameter tables (__sincosf), warp-shuffle basis evolution
//    (all 8 warps, one amplitude/lane, 2 columns/warp) -> Wsh[16][16].
//  - Per chunk: p = real encoding tensor; psi = W @ p (512 FMA); measurement
//    with RX(beta2) folded in (z'=cb*z+sb*y, y'=cb*y-sb*z; T==1 unitarity).
// Circuit reductions (verified vs round-3 literal oracle):
//  - RZ*RY*RX(w) -> one 2x2 U per (L,q); RX(beta0/1) folded into next U.
//  - reference's _apmcx == swap amplitudes 7<->15 -> H/X/MCX block ==
//    psi_i -= sum(psi9,11,13,15)/2 on {9,11,13,15}.
//  - CX-RZ(gamma)-CX chain == 16-entry diagonal phase table.
// Bit convention: qubit q <-> mask (8 >> q), qubit 0 = MSB.

#define NQ 4
#define NL 3
#define TPB 256
#define CHUNKS 4
#define TARGET_BLOCKS 296   // 2 x 148 SMs

struct PS {
    float2 U[NL][NQ][2][2];
    float  ce[NL][NQ], se[NL][NQ];
    float2 dg[NL][16];
};

__device__ __forceinline__ float2 cmulh(float2 a, float2 b) {
    return make_float2(a.x * b.x - a.y * b.y, a.x * b.y + a.y * b.x);
}
__device__ __forceinline__ float2 caddh(float2 a, float2 b) {
    return make_float2(a.x + b.x, a.y + b.y);
}

__global__ void __launch_bounds__(TPB)
vqc_kernel(const float4* __restrict__ x,
           float* __restrict__ out,
           const float* __restrict__ w,
           const float* __restrict__ ew,
           const float* __restrict__ gam,
           const float* __restrict__ bet,
           int n, int base_chunks, int rem) {
    __shared__ PS ps;
    __shared__ float2 Wsh[16][16];
    __shared__ float2 mbsh;

    int t = threadIdx.x;
    int bid = blockIdx.x;

    // contiguous chunk range: first `rem` blocks take base_chunks+1
    int extra = (bid < rem) ? bid : rem;
    int start = bid * base_chunks + extra;
    int cnt   = base_chunks + (bid < rem ? 1 : 0);

    // ---- prefetch all (<=CHUNKS) inputs; hidden behind tables+evolution ----
    float4 xv[CHUNKS];
    bool act[CHUNKS];
    #pragma unroll
    for (int c = 0; c < CHUNKS; c++) {
        int e = (start + c) * TPB + t;
        act[c] = (c < cnt) && (e < n);
        xv[c] = act[c] ? x[e] : make_float4(0.f, 0.f, 0.f, 0.f);
    }

    // ---- parameter tables (per block, parallel, __sincosf) ----
    if (t < NL * NQ) {
        int L = t / NQ, q = t % NQ;
        float th = w[L * NQ + q];
        float c, s;
        __sincosf(0.5f * th, &s, &c);
        float2 RX[2][2] = {{{c, 0.f}, {0.f, -s}}, {{0.f, -s}, {c, 0.f}}};
        float2 RY[2][2] = {{{c, 0.f}, {-s, 0.f}}, {{s, 0.f}, {c, 0.f}}};
        float2 RZ[2][2] = {{{c, -s}, {0.f, 0.f}}, {{0.f, 0.f}, {c, s}}};
        float2 T[2][2], M[2][2];
        #pragma unroll
        for (int i = 0; i < 2; i++)
            #pragma unroll
            for (int j = 0; j < 2; j++)
                T[i][j] = caddh(cmulh(RY[i][0], RX[0][j]),
                                cmulh(RY[i][1], RX[1][j]));
        #pragma unroll
        for (int i = 0; i < 2; i++)
            #pragma unroll
            for (int j = 0; j < 2; j++)
                M[i][j] = caddh(cmulh(RZ[i][0], T[0][j]),
                                cmulh(RZ[i][1], T[1][j]));
        if (L > 0) {  // fold previous layer's RX(beta): M_eff = M * RXb
            float cb, sb;
            __sincosf(0.5f * bet[L - 1], &sb, &cb);
            float2 RXb[2][2] = {{{cb, 0.f}, {0.f, -sb}},
                                {{0.f, -sb}, {cb, 0.f}}};
            float2 E[2][2];
            #pragma unroll
            for (int i = 0; i < 2; i++)
                #pragma unroll
                for (int j = 0; j < 2; j++)
                    E[i][j] = caddh(cmulh(M[i][0], RXb[0][j]),
                                    cmulh(M[i][1], RXb[1][j]));
            #pragma unroll
            for (int i = 0; i < 2; i++)
                #pragma unroll
                for (int j = 0; j < 2; j++)
                    M[i][j] = E[i][j];
        }
        #pragma unroll
        for (int i = 0; i < 2; i++)
            #pragma unroll
            for (int j = 0; j < 2; j++)
                ps.U[L][q][i][j] = M[i][j];
        __sincosf(0.5f * ew[L * NQ + q], &ps.se[L][q], &ps.ce[L][q]);
    }
    if (t >= 16 && t < 16 + NL * 16) {
        int r = t - 16;
        int L = r / 16, idx = r % 16;
        int k = 0;
        #pragma unroll
        for (int i = 0; i < 3; i++) {
            int bi = (idx >> (3 - i)) & 1;
            int bj = (idx >> (2 - i)) & 1;
            if (bi == bj) k++;
        }
        float ang = 0.5f * gam[L] * (float)(3 - 2 * k);
        float sa, ca;
        __sincosf(ang, &sa, &ca);
        ps.dg[L][idx] = make_float2(ca, sa);
    }
    if (t == 64) {
        float cb, sb;
        __sincosf(bet[NL - 1], &sb, &cb);  // FULL angle
        mbsh = make_float2(cb, sb);
    }
    __syncthreads();

    // ---- warp-shuffle basis evolution: all 8 warps, 2 columns each ----
    {
        int lane = t & 31;
        int i = lane & 15;                       // amplitude index
        int col = ((t >> 5) << 1) | (lane >> 4); // basis column 0..15
        float ax = (i == col) ? 1.f : 0.f;
        float ay = 0.f;

        #pragma unroll
        for (int L = 0; L < NL; L++) {
            // combined single-qubit U per qubit (butterfly over mask)
            #pragma unroll
            for (int q = 0; q < NQ; q++) {
                int m = 8 >> q;
                float2 u00 = ps.U[L][q][0][0], u01 = ps.U[L][q][0][1];
                float2 u10 = ps.U[L][q][1][0], u11 = ps.U[L][q][1][1];
                bool bit = (i & m) != 0;
                float csx = bit ? u11.x : u00.x, csy = bit ? u11.y : u00.y;
                float cpx = bit ? u10.x : u01.x, cpy = bit ? u10.y : u01.y;
                float px = __shfl_xor_sync(0xffffffffu, ax, m);
                float py = __shfl_xor_sync(0xffffffffu, ay, m);
                float nr = csx * ax;
                nr = fmaf(-csy, ay, nr);
                nr = fmaf(cpx, px, nr);
                nr = fmaf(-cpy, py, nr);
                float ni = csx * ay;
                ni = fmaf(csy, ax, ni);
                ni = fmaf(cpx, py, ni);
                ni = fmaf(cpy, px, ni);
                ax = nr; ay = ni;
            }
            // cRX ring: control q, target (q+1)%4 (RX symmetric -> uniform)
            #pragma unroll
            for (int q = 0; q < NQ; q++) {
                int cm = 8 >> q;
                int tm = 8 >> ((q + 1) & 3);
                float c = ps.ce[L][q], s = ps.se[L][q];
                bool on = (i & cm) != 0;
                float ce_ = on ? c : 1.f;
                float se_ = on ? s : 0.f;
                float px = __shfl_xor_sync(0xffffffffu, ax, tm);
                float py = __shfl_xor_sync(0xffffffffu, ay, tm);
                float nr = fmaf(ce_, ax, se_ * py);
                float ni = fmaf(ce_, ay, -se_ * px);
                ax = nr; ay = ni;
            }
            // diffuser: psi_i -= (psi9+psi11+psi13+psi15)/2, i in {9,11,13,15}
            {
                bool sel = ((i & 9) == 9);
                float h = sel ? 0.5f : 0.f;
                float vx = sel ? ax : 0.f;
                float vy = sel ? ay : 0.f;
                vx += __shfl_xor_sync(0xffffffffu, vx, 2);
                vy += __shfl_xor_sync(0xffffffffu, vy, 2);
                vx += __shfl_xor_sync(0xffffffffu, vx, 4);
                vy += __shfl_xor_sync(0xffffffffu, vy, 4);
                ax = fmaf(-h, vx, ax);
                ay = fmaf(-h, vy, ay);
            }
            // RZZ diagonal phase
            {
                float2 ph = ps.dg[L][i];
                float nr = ph.x * ax; nr = fmaf(-ph.y, ay, nr);
                float ni = ph.x * ay; ni = fmaf(ph.y, ax, ni);
                ax = nr; ay = ni;
            }
        }
        Wsh[i][col] = make_float2(ax, ay);
    }
    __syncthreads();

    float cb = mbsh.x, sb = mbsh.y;

    // ---- body: up to CHUNKS chunks per block (STATIC unroll) ----
    #pragma unroll
    for (int c = 0; c < CHUNKS; c++) {
        if (!act[c]) continue;

        // encode: p = tensor_q (cos x_q/2, sin x_q/2), real
        float p[16];
        {
            float cq[4], sq[4];
            __sincosf(0.5f * xv[c].x, &sq[0], &cq[0]);
            __sincosf(0.5f * xv[c].y, &sq[1], &cq[1]);
            __sincosf(0.5f * xv[c].z, &sq[2], &cq[2]);
            __sincosf(0.5f * xv[c].w, &sq[3], &cq[3]);
            float a01[4], a012[8];
            a01[0] = cq[0] * cq[1]; a01[1] = cq[0] * sq[1];
            a01[2] = sq[0] * cq[1]; a01[3] = sq[0] * sq[1];
            #pragma unroll
            for (int k = 0; k < 4; k++) {
                a012[2 * k]     = a01[k] * cq[2];
                a012[2 * k + 1] = a01[k] * sq[2];
            }
            #pragma unroll
            for (int m = 0; m < 8; m++) {
                p[2 * m]     = a012[m] * cq[3];
                p[2 * m + 1] = a012[m] * sq[3];
            }
        }

        // psi = W @ p (complex x real matvec, 512 FMA)
        float2 psi[16];
        #pragma unroll
        for (int i = 0; i < 16; i++) {
            const float4* row = reinterpret_cast<const float4*>(&Wsh[i][0]);
            float re = 0.f, im = 0.f;
            #pragma unroll
            for (int jj = 0; jj < 8; jj++) {
                float4 v = row[jj];  // (W[i][2jj].re,.im, W[i][2jj+1].re,.im)
                re = fmaf(v.x, p[2 * jj], re);
                im = fmaf(v.y, p[2 * jj], im);
                re = fmaf(v.z, p[2 * jj + 1], re);
                im = fmaf(v.w, p[2 * jj + 1], im);
            }
            psi[i] = make_float2(re, im);
        }

        // measurement with RX(beta2) fold; T == 1 by unitarity
        float sq2[16];
        #pragma unroll
        for (int i = 0; i < 16; i++)
            sq2[i] = fmaf(psi[i].x, psi[i].x, psi[i].y * psi[i].y);

        float res[12];
        #pragma unroll
        for (int q = 0; q < NQ; q++) {
            int mask = 8 >> q;
            float s1 = 0.f;
            #pragma unroll
            for (int i = 0; i < 16; i++)
                if (i & mask) s1 += sq2[i];
            float z = fmaf(-2.f, s1, 1.f);

            float xr = 0.f, yi = 0.f;
            #pragma unroll
            for (int i = 0; i < 16; i++) {
                if (i & mask) continue;
                int j = i | mask;
                float2 a = psi[i], d = psi[j];
                xr = fmaf(a.x, d.x, xr); xr = fmaf(a.y, d.y, xr);
                yi = fmaf(a.x, d.y, yi); yi = fmaf(-a.y, d.x, yi);
            }
            float xo = 2.f * xr, yo = 2.f * yi;
            res[q]     = fmaf(cb, z, sb * yo);      // z' = cb*z + sb*y
            res[4 + q] = xo;                        // x' = x
            res[8 + q] = fmaf(cb, yo, -sb * z);     // y' = cb*y - sb*z
        }

        int e = (start + c) * TPB + t;
        float4* o = reinterpret_cast<float4*>(out + (size_t)e * 12);
        o[0] = make_float4(res[0], res[1], res[2],  res[3]);
        o[1] = make_float4(res[4], res[5], res[6],  res[7]);
        o[2] = make_float4(res[8], res[9], res[10], res[11]);
    }
}

extern "C" void kernel_launch(void* const* d_in, const int* in_sizes, int n_in,
                              void* d_out, int out_size) {
    const float* x   = (const float*)d_in[0];  // (B, 4)
    const float* w   = (const float*)d_in[1];  // (3, 4)
    const float* ew  = (const float*)d_in[2];  // (3, 4)
    const float* gam = (const float*)d_in[3];  // (3,)
    const float* bet = (const float*)d_in[4];  // (3,)
    float* out = (float*)d_out;                // (B, 12)

    int n = in_sizes[0] / 4;
    int total_chunks = (n + TPB - 1) / TPB;

    int blocks = TARGET_BLOCKS;
    if (blocks > total_chunks) blocks = total_chunks;
    int base_chunks = total_chunks / blocks;
    int rem = total_chunks % blocks;
    // guard: static unroll covers at most CHUNKS chunks per block
    while (base_chunks + (rem ? 1 : 0) > CHUNKS) {
        blocks += 32;
        base_chunks = total_chunks / blocks;
        rem = total_chunks % blocks;
    }

    vqc_kernel<<<blocks, TPB>>>((const float4*)x, out, w, ew, gam, bet,
                                n, base_chunks, rem);
}